// round 15
// baseline (speedup 1.0000x reference)
#include <cuda_runtime.h>
#include <cuda_bf16.h>
#include <cuda_fp16.h>
#include <cstdint>

#define NN 20000
#define NE 320000
#define KEXT 768

// ---------------- scratch (device globals; no runtime allocation) ----------
__device__ __align__(16) __half g_feat1h[NN * 256];  // layer1 feats, fp16 (gather)
__device__ __align__(16) __half g_feat2h[NN * 64];   // layer2 feats, fp16 (gather)
__device__ float g_el1[NN * 4];
__device__ float g_er1[NN * 4];
__device__ float g_el2[NN];
__device__ float g_er2[NN];
__device__ int   g_counts[NN];
__device__ int   g_row_off[NN + 1];
__device__ int   g_cursor[NN];
__device__ int   g_csr_src[NE];
// split GEMM operands: A2 = [hi(256) | lo(256)] bf16 per row; Bx = [hi;lo;hi]
__device__ __align__(16) __nv_bfloat16 g_A2[NN * 512];
__device__ __align__(16) __nv_bfloat16 g_Bx1[KEXT * 256];
__device__ __align__(16) __nv_bfloat16 g_Bx2[KEXT * 64];

// ---------------- PTX helpers ----------------------------------------------
__device__ __forceinline__ uint32_t smem_u32(const void* p) {
    uint32_t a;
    asm("{ .reg .u64 t; cvta.to.shared.u64 t, %1; cvt.u32.u64 %0, t; }"
        : "=r"(a) : "l"(p));
    return a;
}

__device__ __forceinline__ void cp16(uint32_t dst, const void* src, bool pred) {
    asm volatile("cp.async.cg.shared.global [%0], [%1], 16, %2;"
                 :: "r"(dst), "l"(src), "r"(pred ? 16 : 0));
}
#define CP_COMMIT() asm volatile("cp.async.commit_group;" ::: "memory")

#define LDSM_X4(r0, r1, r2, r3, addr) \
    asm volatile("ldmatrix.sync.aligned.m8n8.x4.shared.b16 {%0,%1,%2,%3}, [%4];" \
                 : "=r"(r0), "=r"(r1), "=r"(r2), "=r"(r3) : "r"(addr))
#define LDSM_X4_T(r0, r1, r2, r3, addr) \
    asm volatile("ldmatrix.sync.aligned.m8n8.x4.trans.shared.b16 {%0,%1,%2,%3}, [%4];" \
                 : "=r"(r0), "=r"(r1), "=r"(r2), "=r"(r3) : "r"(addr))

#define MMA_BF16(d, a, b) \
    asm volatile("mma.sync.aligned.m16n8k16.row.col.f32.bf16.bf16.f32 " \
                 "{%0,%1,%2,%3}, {%4,%5,%6,%7}, {%8,%9}, {%0,%1,%2,%3};" \
                 : "+f"((d)[0]), "+f"((d)[1]), "+f"((d)[2]), "+f"((d)[3]) \
                 : "r"((a)[0]), "r"((a)[1]), "r"((a)[2]), "r"((a)[3]), \
                   "r"((b)[0]), "r"((b)[1]))

__device__ __forceinline__ void split_pack(float x0, float x1, uint32_t& hp, uint32_t& lp) {
    __nv_bfloat16 h0 = __float2bfloat16(x0);
    __nv_bfloat16 h1 = __float2bfloat16(x1);
    __nv_bfloat16 l0 = __float2bfloat16(x0 - __bfloat162float(h0));
    __nv_bfloat16 l1 = __float2bfloat16(x1 - __bfloat162float(h1));
    hp = ((uint32_t)__bfloat16_as_ushort(h1) << 16) | __bfloat16_as_ushort(h0);
    lp = ((uint32_t)__bfloat16_as_ushort(l1) << 16) | __bfloat16_as_ushort(l0);
}

// ---------------- fused prep kernel: count || convA || convB1 || convB2 -----
#define NB_COUNT 313
#define NB_CONVA 2500
#define NB_CONVB1 768
#define NB_CONVB2 192
#define NB_PREP (NB_COUNT + NB_CONVA + NB_CONVB1 + NB_CONVB2)

__device__ __forceinline__ void convB_body(const float* __restrict__ W,
                                           __nv_bfloat16* __restrict__ Bx,
                                           int t, int NOUT) {
    int r = t / NOUT, n = t - r * NOUT;
    int seg = r >> 8, k = r & 255;
    float w = W[(size_t)k * NOUT + n];
    __nv_bfloat16 hi = __float2bfloat16(w);
    Bx[t] = (seg == 1) ? __float2bfloat16(w - __bfloat162float(hi)) : hi;
}

__global__ __launch_bounds__(256) void prep_kernel(
    const int4* __restrict__ dst4, const float* __restrict__ in_feat,
    const float* __restrict__ W1, const float* __restrict__ W2) {
    const int tid = threadIdx.x;
    int b = blockIdx.x;
    if (b < NB_COUNT) {
        int t = b * 256 + tid;
        if (t < NE / 4) {
            int4 d = dst4[t];
            atomicAdd(&g_counts[d.x], 1);
            atomicAdd(&g_counts[d.y], 1);
            atomicAdd(&g_counts[d.z], 1);
            atomicAdd(&g_counts[d.w], 1);
        }
    } else if (b < NB_COUNT + NB_CONVA) {
        int t = (b - NB_COUNT) * 256 + tid;
        int row = t >> 5, c8 = t & 31;
        const float4* p = (const float4*)(in_feat + (size_t)row * 256 + c8 * 8);
        float4 v0 = p[0], v1 = p[1];
        uint32_t hp[4], lp[4];
        split_pack(v0.x, v0.y, hp[0], lp[0]);
        split_pack(v0.z, v0.w, hp[1], lp[1]);
        split_pack(v1.x, v1.y, hp[2], lp[2]);
        split_pack(v1.z, v1.w, hp[3], lp[3]);
        *(uint4*)(g_A2 + (size_t)row * 512 + c8 * 8)       = make_uint4(hp[0], hp[1], hp[2], hp[3]);
        *(uint4*)(g_A2 + (size_t)row * 512 + 256 + c8 * 8) = make_uint4(lp[0], lp[1], lp[2], lp[3]);
    } else if (b < NB_COUNT + NB_CONVA + NB_CONVB1) {
        int t = (b - NB_COUNT - NB_CONVA) * 256 + tid;
        convB_body(W1, g_Bx1, t, 256);
    } else {
        int t = (b - NB_COUNT - NB_CONVA - NB_CONVB1) * 256 + tid;
        convB_body(W2, g_Bx2, t, 64);
    }
}

// ---------------- scan (row offsets) ----------------------------------------
__global__ void scan_kernel() {
    __shared__ int ssum[1024];
    const int tid = threadIdx.x;
    const int CH  = (NN + 1023) / 1024;
    const int base = tid * CH;
    int s = 0;
    for (int i = 0; i < CH; i++) {
        int idx = base + i;
        if (idx < NN) s += g_counts[idx];
    }
    ssum[tid] = s;
    __syncthreads();
    for (int off = 1; off < 1024; off <<= 1) {
        int v = 0;
        if (tid >= off) v = ssum[tid - off];
        __syncthreads();
        ssum[tid] += v;
        __syncthreads();
    }
    int run = (tid == 0) ? 0 : ssum[tid - 1];
    for (int i = 0; i < CH; i++) {
        int idx = base + i;
        if (idx < NN) {
            g_row_off[idx] = run;
            g_cursor[idx]  = run;
            run += g_counts[idx];
        }
    }
    if (tid == 0) g_row_off[NN] = ssum[1023];
}

// ---------------- GEMM block device function --------------------------------
// A2: [NN,512] hi|lo.  Bx: [768,NOUT].  k_ext segs: (Ahi,Bhi),(Ahi,Blo),(Alo,Bhi)
template <int BM, int BN, int STAGES>
struct __align__(16) GemmSmem {
    __nv_bfloat16 As[STAGES][BM * 40];  // 80B padded rows (BK=32)
    __nv_bfloat16 Bs[STAGES][32 * BN];
    float s_el[(BN / 64) * BM], s_er[(BN / 64) * BM];
    float s_al[BN], s_ar[BN];
};

template <int BM, int BN, int WARPS_M, int WARPS_N, int TOTHEADS, int STAGES>
__device__ void gemm_block(
    int bxx, int byy, GemmSmem<BM, BN, STAGES>& S,
    const __nv_bfloat16* __restrict__ Bx, __half* __restrict__ Fh,
    const float* __restrict__ al, const float* __restrict__ ar,
    float* __restrict__ elo, float* __restrict__ ero, int NOUT) {
    constexpr int WM = BM / WARPS_M;
    constexpr int WN = BN / WARPS_N;
    constexpr int MI = WM / 16;
    constexpr int NI = WN / 8;
    constexpr int BCH = BN / 8;
    constexpr int NK = KEXT / 32;        // 24
    constexpr int HPB = BN / 64;

    const int tid = threadIdx.x;
    const int warp = tid >> 5, lane = tid & 31;
    const int wm = warp / WARPS_N, wn = warp % WARPS_N;
    const int m0 = byy * BM;
    const int n0 = bxx * BN;

    for (int i = tid; i < HPB * BM; i += 256) { S.s_el[i] = 0.f; S.s_er[i] = 0.f; }
    for (int i = tid; i < BN; i += 256) { S.s_al[i] = al[n0 + i]; S.s_ar[i] = ar[n0 + i]; }

    uint32_t asb[STAGES], bsb[STAGES];
#pragma unroll
    for (int s = 0; s < STAGES; s++) {
        asb[s] = smem_u32(&S.As[s][0]);
        bsb[s] = smem_u32(&S.Bs[s][0]);
    }

    float acc[MI][NI][4];
#pragma unroll
    for (int mi = 0; mi < MI; mi++)
#pragma unroll
        for (int ni = 0; ni < NI; ni++)
#pragma unroll
            for (int q = 0; q < 4; q++) acc[mi][ni][q] = 0.f;

    auto load_stage = [&](int kt, int buf) {
        int k0e = kt * 32;
        int seg = k0e >> 8;
        int acol = ((seg == 2) ? 256 : 0) + (k0e & 255);
#pragma unroll
        for (int i = tid; i < BM * 4; i += 256) {
            int r = i >> 2, c = i & 3;
            cp16(asb[buf] + r * 80 + c * 16,
                 g_A2 + (size_t)(m0 + r) * 512 + acol + c * 8,
                 (m0 + r) < NN);
        }
#pragma unroll
        for (int i = tid; i < 32 * BCH; i += 256) {
            int r = i / BCH, c = i - r * BCH;
            int cp = c ^ (r & 7);
            cp16(bsb[buf] + r * (BN * 2) + cp * 16,
                 Bx + (size_t)(k0e + r) * NOUT + n0 + c * 8, true);
        }
        CP_COMMIT();
    };

#pragma unroll
    for (int s = 0; s < STAGES - 1; s++) load_stage(s, s);

    for (int kt = 0; kt < NK; kt++) {
        if constexpr (STAGES == 2)
            asm volatile("cp.async.wait_group 0;" ::: "memory");
        else if constexpr (STAGES == 3)
            asm volatile("cp.async.wait_group 1;" ::: "memory");
        else
            asm volatile("cp.async.wait_group 2;" ::: "memory");
        __syncthreads();
        if (kt + STAGES - 1 < NK) load_stage(kt + STAGES - 1, (kt + STAGES - 1) % STAGES);
        const int buf = kt % STAGES;

#pragma unroll
        for (int ks = 0; ks < 32; ks += 16) {
            uint32_t af[MI][4];
#pragma unroll
            for (int mi = 0; mi < MI; mi++) {
                int row = wm * WM + mi * 16 + (lane & 15);
                int ch = (ks >> 3) + (lane >> 4);
                LDSM_X4(af[mi][0], af[mi][1], af[mi][2], af[mi][3],
                        asb[buf] + row * 80 + ch * 16);
            }
            uint32_t bfr[NI][2];
#pragma unroll
            for (int ni2 = 0; ni2 < NI / 2; ni2++) {
                int krow = ks + (lane & 7) + ((lane >> 3) & 1) * 8;
                int c = (wn * WN) / 8 + ni2 * 2 + (lane >> 4);
                int cp = c ^ (krow & 7);
                uint32_t r0, r1, r2, r3;
                LDSM_X4_T(r0, r1, r2, r3, bsb[buf] + krow * (BN * 2) + cp * 16);
                bfr[ni2 * 2][0] = r0; bfr[ni2 * 2][1] = r1;
                bfr[ni2 * 2 + 1][0] = r2; bfr[ni2 * 2 + 1][1] = r3;
            }
#pragma unroll
            for (int mi = 0; mi < MI; mi++)
#pragma unroll
                for (int ni = 0; ni < NI; ni++)
                    MMA_BF16(acc[mi][ni], af[mi], bfr[ni]);
        }
    }

    // epilogue: fp16 feat store + fused el/er
#pragma unroll
    for (int mi = 0; mi < MI; mi++) {
        int lrow = wm * WM + mi * 16 + (lane >> 2);
        int grow = m0 + lrow;
        float el0 = 0.f, er0 = 0.f, el8 = 0.f, er8 = 0.f;
#pragma unroll
        for (int ni = 0; ni < NI; ni++) {
            int lcol = wn * WN + ni * 8 + (lane & 3) * 2;
            int gcol = n0 + lcol;
            float av0 = S.s_al[lcol], av1 = S.s_al[lcol + 1];
            float rv0 = S.s_ar[lcol], rv1 = S.s_ar[lcol + 1];
            el0 += acc[mi][ni][0] * av0 + acc[mi][ni][1] * av1;
            er0 += acc[mi][ni][0] * rv0 + acc[mi][ni][1] * rv1;
            el8 += acc[mi][ni][2] * av0 + acc[mi][ni][3] * av1;
            er8 += acc[mi][ni][2] * rv0 + acc[mi][ni][3] * rv1;
            if (grow < NN)
                *(__half2*)(Fh + (size_t)grow * NOUT + gcol) =
                    __floats2half2_rn(acc[mi][ni][0], acc[mi][ni][1]);
            if (grow + 8 < NN)
                *(__half2*)(Fh + (size_t)(grow + 8) * NOUT + gcol) =
                    __floats2half2_rn(acc[mi][ni][2], acc[mi][ni][3]);
        }
#pragma unroll
        for (int off = 1; off <= 2; off <<= 1) {
            el0 += __shfl_xor_sync(0xffffffffu, el0, off);
            er0 += __shfl_xor_sync(0xffffffffu, er0, off);
            el8 += __shfl_xor_sync(0xffffffffu, el8, off);
            er8 += __shfl_xor_sync(0xffffffffu, er8, off);
        }
        if ((lane & 3) == 0) {
            int hl = (wn * WN) >> 6;
            if (grow < NN) {
                atomicAdd(&S.s_el[hl * BM + lrow], el0);
                atomicAdd(&S.s_er[hl * BM + lrow], er0);
            }
            if (grow + 8 < NN) {
                atomicAdd(&S.s_el[hl * BM + lrow + 8], el8);
                atomicAdd(&S.s_er[hl * BM + lrow + 8], er8);
            }
        }
    }
    __syncthreads();
    for (int i = tid; i < HPB * BM; i += 256) {
        int hl = i / BM, r = i % BM;
        int grow = m0 + r;
        if (grow < NN) {
            int gh = (n0 >> 6) + hl;
            elo[grow * TOTHEADS + gh] = S.s_el[i];
            ero[grow * TOTHEADS + gh] = S.s_er[i];
        }
    }
}

// ---------------- fused scatter || GEMM1 (BM=64, 3-stage, static smem) ------
#define NB_GEMM1 626   // 2 x 313

__global__ __launch_bounds__(256) void scatter_gemm1_kernel(
    const int4* __restrict__ src4, const int4* __restrict__ dst4,
    const __nv_bfloat16* __restrict__ Bx, __half* __restrict__ Fh,
    const float* __restrict__ al, const float* __restrict__ ar,
    float* __restrict__ elo, float* __restrict__ ero) {
    __shared__ GemmSmem<64, 128, 3> S;
    int b = blockIdx.x;
    if (b < NB_GEMM1) {
        gemm_block<64, 128, 4, 2, 4, 3>(b & 1, b >> 1, S, Bx, Fh, al, ar, elo, ero, 256);
    } else {
        int t = (b - NB_GEMM1) * 256 + threadIdx.x;
        if (t < NE / 4) {
            int4 s = src4[t];
            int4 d = dst4[t];
            g_csr_src[atomicAdd(&g_cursor[d.x], 1)] = s.x;
            g_csr_src[atomicAdd(&g_cursor[d.y], 1)] = s.y;
            g_csr_src[atomicAdd(&g_cursor[d.z], 1)] = s.z;
            g_csr_src[atomicAdd(&g_cursor[d.w], 1)] = s.w;
        }
    }
}

// gemm2: BM=64 tiles (313 CTAs), 4-stage pipeline, 4x2 warp grid (static smem)
__global__ __launch_bounds__(256) void gemm2_kernel(
    const __nv_bfloat16* __restrict__ Bx, __half* __restrict__ Fh,
    const float* __restrict__ al, const float* __restrict__ ar,
    float* __restrict__ elo, float* __restrict__ ero) {
    __shared__ GemmSmem<64, 64, 4> S;
    gemm_block<64, 64, 4, 2, 1, 4>(0, blockIdx.x, S, Bx, Fh, al, ar, elo, ero, 64);
}

// ---------------- layer-1 softmax-aggregate + bias + ELU -> split-bf16 A2 ---
// 1 warp per node; 8 lanes/head, 8 feats/lane (uint4 gathers).
// max-shift dropped: logits bounded, exp cannot overflow, softmax shift-invariant
__global__ void agg1_kernel(const float* __restrict__ b1) {
    int gw   = (blockIdx.x * blockDim.x + threadIdx.x) >> 5;
    int lane = threadIdx.x & 31;
    if (gw >= NN) return;
    const int beg = g_row_off[gw];
    const int end = g_row_off[gw + 1];
    const int head = lane >> 3;
    const int f0   = lane * 8;
    const float er = g_er1[gw * 4 + head];

    float acc[8];
#pragma unroll
    for (int j = 0; j < 8; j++) acc[j] = 0.f;
    float den = 0.f;

    int i = beg;
    for (; i + 4 <= end; i += 4) {
        int s0 = g_csr_src[i],     s1 = g_csr_src[i + 1];
        int s2 = g_csr_src[i + 2], s3 = g_csr_src[i + 3];
        float e0 = g_el1[s0 * 4 + head] + er;
        float e1 = g_el1[s1 * 4 + head] + er;
        float e2 = g_el1[s2 * 4 + head] + er;
        float e3 = g_el1[s3 * 4 + head] + er;
        e0 = (e0 > 0.f) ? e0 : 0.2f * e0;
        e1 = (e1 > 0.f) ? e1 : 0.2f * e1;
        e2 = (e2 > 0.f) ? e2 : 0.2f * e2;
        e3 = (e3 > 0.f) ? e3 : 0.2f * e3;
        float x0 = __expf(e0), x1 = __expf(e1), x2 = __expf(e2), x3 = __expf(e3);
        den += (x0 + x1) + (x2 + x3);
        uint4 u0 = *(const uint4*)(g_feat1h + (size_t)s0 * 256 + f0);
        uint4 u1 = *(const uint4*)(g_feat1h + (size_t)s1 * 256 + f0);
        uint4 u2 = *(const uint4*)(g_feat1h + (size_t)s2 * 256 + f0);
        uint4 u3 = *(const uint4*)(g_feat1h + (size_t)s3 * 256 + f0);
        const __half2* h0 = (const __half2*)&u0;
        const __half2* h1 = (const __half2*)&u1;
        const __half2* h2 = (const __half2*)&u2;
        const __half2* h3 = (const __half2*)&u3;
#pragma unroll
        for (int q = 0; q < 4; q++) {
            float2 v0 = __half22float2(h0[q]);
            float2 v1 = __half22float2(h1[q]);
            float2 v2 = __half22float2(h2[q]);
            float2 v3 = __half22float2(h3[q]);
            acc[2 * q]     = fmaf(x0, v0.x, fmaf(x1, v1.x, fmaf(x2, v2.x, fmaf(x3, v3.x, acc[2 * q]))));
            acc[2 * q + 1] = fmaf(x0, v0.y, fmaf(x1, v1.y, fmaf(x2, v2.y, fmaf(x3, v3.y, acc[2 * q + 1]))));
        }
    }
    for (; i < end; i++) {
        int s = g_csr_src[i];
        float e = g_el1[s * 4 + head] + er;
        e = (e > 0.f) ? e : 0.2f * e;
        float ex = __expf(e);
        den += ex;
        uint4 u = *(const uint4*)(g_feat1h + (size_t)s * 256 + f0);
        const __half2* hh = (const __half2*)&u;
#pragma unroll
        for (int q = 0; q < 4; q++) {
            float2 v = __half22float2(hh[q]);
            acc[2 * q]     = fmaf(ex, v.x, acc[2 * q]);
            acc[2 * q + 1] = fmaf(ex, v.y, acc[2 * q + 1]);
        }
    }

    float inv = (den > 0.f) ? (1.0f / den) : 0.f;
    float o[8];
#pragma unroll
    for (int j = 0; j < 8; j++) {
        float v = acc[j] * inv + b1[f0 + j];
        o[j] = (v > 0.f) ? v : (__expf(v) - 1.0f);   // ELU
    }
    // write split-bf16 A2 row directly (layer2 GEMM operand)
    uint32_t hp[4], lp[4];
    split_pack(o[0], o[1], hp[0], lp[0]);
    split_pack(o[2], o[3], hp[1], lp[1]);
    split_pack(o[4], o[5], hp[2], lp[2]);
    split_pack(o[6], o[7], hp[3], lp[3]);
    *(uint4*)(g_A2 + (size_t)gw * 512 + f0)       = make_uint4(hp[0], hp[1], hp[2], hp[3]);
    *(uint4*)(g_A2 + (size_t)gw * 512 + 256 + f0) = make_uint4(lp[0], lp[1], lp[2], lp[3]);
}

// ---------------- layer-2 softmax-aggregate + bias --------------------------
__global__ void agg2_kernel(const float* __restrict__ b2, float* __restrict__ out) {
    int gw   = (blockIdx.x * blockDim.x + threadIdx.x) >> 5;
    int lane = threadIdx.x & 31;
    if (gw >= NN) return;
    const int beg = g_row_off[gw];
    const int end = g_row_off[gw + 1];
    const float er = g_er2[gw];

    float a0 = 0.f, a1 = 0.f, den = 0.f;
    int i = beg;
    for (; i + 4 <= end; i += 4) {
        int s0 = g_csr_src[i],     s1 = g_csr_src[i + 1];
        int s2 = g_csr_src[i + 2], s3 = g_csr_src[i + 3];
        float e0 = g_el2[s0] + er, e1 = g_el2[s1] + er;
        float e2 = g_el2[s2] + er, e3 = g_el2[s3] + er;
        e0 = (e0 > 0.f) ? e0 : 0.2f * e0;
        e1 = (e1 > 0.f) ? e1 : 0.2f * e1;
        e2 = (e2 > 0.f) ? e2 : 0.2f * e2;
        e3 = (e3 > 0.f) ? e3 : 0.2f * e3;
        float x0 = __expf(e0), x1 = __expf(e1), x2 = __expf(e2), x3 = __expf(e3);
        den += (x0 + x1) + (x2 + x3);
        float2 v0 = __half22float2(*(const __half2*)(g_feat2h + (size_t)s0 * 64 + lane * 2));
        float2 v1 = __half22float2(*(const __half2*)(g_feat2h + (size_t)s1 * 64 + lane * 2));
        float2 v2 = __half22float2(*(const __half2*)(g_feat2h + (size_t)s2 * 64 + lane * 2));
        float2 v3 = __half22float2(*(const __half2*)(g_feat2h + (size_t)s3 * 64 + lane * 2));
        a0 = fmaf(x0, v0.x, fmaf(x1, v1.x, fmaf(x2, v2.x, fmaf(x3, v3.x, a0))));
        a1 = fmaf(x0, v0.y, fmaf(x1, v1.y, fmaf(x2, v2.y, fmaf(x3, v3.y, a1))));
    }
    for (; i < end; i++) {
        int s = g_csr_src[i];
        float e = g_el2[s] + er;
        e = (e > 0.f) ? e : 0.2f * e;
        float ex = __expf(e);
        den += ex;
        float2 v = __half22float2(*(const __half2*)(g_feat2h + (size_t)s * 64 + lane * 2));
        a0 = fmaf(ex, v.x, a0);
        a1 = fmaf(ex, v.y, a1);
    }
    float inv = (den > 0.f) ? (1.0f / den) : 0.f;
    float2 r = make_float2(a0 * inv + b2[lane * 2], a1 * inv + b2[lane * 2 + 1]);
    *(float2*)(out + (size_t)gw * 64 + lane * 2) = r;
}

// ---------------- launcher ---------------------------------------------------
extern "C" void kernel_launch(void* const* d_in, const int* in_sizes, int n_in,
                              void* d_out, int out_size) {
    const float* in_feat = (const float*)d_in[0];
    const float* W1      = (const float*)d_in[1];
    const float* al1     = (const float*)d_in[2];
    const float* ar1     = (const float*)d_in[3];
    const float* b1      = (const float*)d_in[4];
    const float* W2      = (const float*)d_in[5];
    const float* al2     = (const float*)d_in[6];
    const float* ar2     = (const float*)d_in[7];
    const float* b2      = (const float*)d_in[8];
    const int*   src     = (const int*)d_in[9];
    const int*   dst     = (const int*)d_in[10];
    float*       out     = (float*)d_out;

    __half *f1h, *f2h;
    float *el1, *er1, *el2, *er2;
    __nv_bfloat16 *bx1, *bx2;
    int* counts;
    cudaGetSymbolAddress((void**)&f1h, g_feat1h);
    cudaGetSymbolAddress((void**)&f2h, g_feat2h);
    cudaGetSymbolAddress((void**)&el1, g_el1);
    cudaGetSymbolAddress((void**)&er1, g_er1);
    cudaGetSymbolAddress((void**)&el2, g_el2);
    cudaGetSymbolAddress((void**)&er2, g_er2);
    cudaGetSymbolAddress((void**)&bx1, g_Bx1);
    cudaGetSymbolAddress((void**)&bx2, g_Bx2);
    cudaGetSymbolAddress((void**)&counts, g_counts);

    // zero counts (memset node)
    cudaMemsetAsync(counts, 0, NN * sizeof(int));

    // K1: count || convA || convB1 || convB2
    prep_kernel<<<NB_PREP, 256>>>((const int4*)dst, in_feat, W1, W2);

    // K2: row-offset scan (1024 threads)
    scan_kernel<<<1, 1024>>>();

    // K3: scatter || GEMM1 (BM=64, 3-stage, 626 GEMM CTAs)
    scatter_gemm1_kernel<<<NB_GEMM1 + NB_COUNT, 256>>>(
        (const int4*)src, (const int4*)dst, bx1, f1h, al1, ar1, el1, er1);

    // K4: layer-1 aggregate -> split-bf16 A2  (1 warp per node)
    agg1_kernel<<<(NN * 32 + 255) / 256, 256>>>(b1);

    // K5: layer-2 GEMM (BM=64, 4-stage pipeline, 313 CTAs)
    gemm2_kernel<<<(NN + 63) / 64, 256>>>(bx2, f2h, al2, ar2, el2, er2);

    // K6: layer-2 aggregate
    agg2_kernel<<<(NN * 32 + 255) / 256, 256>>>(b2, out);
}

// round 16
// speedup vs baseline: 1.0308x; 1.0308x over previous
#include <cuda_runtime.h>
#include <cuda_bf16.h>
#include <cuda_fp16.h>
#include <cstdint>

#define NN 20000
#define NE 320000
#define KEXT 768

// ---------------- scratch (device globals; no runtime allocation) ----------
__device__ __align__(16) __half g_feat1h[NN * 256];  // layer1 feats, fp16 (gather)
__device__ __align__(16) __half g_feat2h[NN * 64];   // layer2 feats, fp16 (gather)
__device__ float g_el1[NN * 4];
__device__ float g_er1[NN * 4];
__device__ float g_el2[NN];
__device__ float g_er2[NN];
__device__ int   g_counts[NN];
__device__ int   g_row_off[NN + 1];
__device__ int   g_cursor[NN];
__device__ int   g_csr_src[NE];
// split GEMM operands: A2 = [hi(256) | lo(256)] bf16 per row; Bx = [hi;lo;hi]
__device__ __align__(16) __nv_bfloat16 g_A2[NN * 512];
__device__ __align__(16) __nv_bfloat16 g_Bx1[KEXT * 256];
__device__ __align__(16) __nv_bfloat16 g_Bx2[KEXT * 64];

// ---------------- PTX helpers ----------------------------------------------
__device__ __forceinline__ uint32_t smem_u32(const void* p) {
    uint32_t a;
    asm("{ .reg .u64 t; cvta.to.shared.u64 t, %1; cvt.u32.u64 %0, t; }"
        : "=r"(a) : "l"(p));
    return a;
}

__device__ __forceinline__ void cp16(uint32_t dst, const void* src, bool pred) {
    asm volatile("cp.async.cg.shared.global [%0], [%1], 16, %2;"
                 :: "r"(dst), "l"(src), "r"(pred ? 16 : 0));
}
#define CP_COMMIT() asm volatile("cp.async.commit_group;" ::: "memory")

#define LDSM_X4(r0, r1, r2, r3, addr) \
    asm volatile("ldmatrix.sync.aligned.m8n8.x4.shared.b16 {%0,%1,%2,%3}, [%4];" \
                 : "=r"(r0), "=r"(r1), "=r"(r2), "=r"(r3) : "r"(addr))
#define LDSM_X4_T(r0, r1, r2, r3, addr) \
    asm volatile("ldmatrix.sync.aligned.m8n8.x4.trans.shared.b16 {%0,%1,%2,%3}, [%4];" \
                 : "=r"(r0), "=r"(r1), "=r"(r2), "=r"(r3) : "r"(addr))

#define MMA_BF16(d, a, b) \
    asm volatile("mma.sync.aligned.m16n8k16.row.col.f32.bf16.bf16.f32 " \
                 "{%0,%1,%2,%3}, {%4,%5,%6,%7}, {%8,%9}, {%0,%1,%2,%3};" \
                 : "+f"((d)[0]), "+f"((d)[1]), "+f"((d)[2]), "+f"((d)[3]) \
                 : "r"((a)[0]), "r"((a)[1]), "r"((a)[2]), "r"((a)[3]), \
                   "r"((b)[0]), "r"((b)[1]))

__device__ __forceinline__ void split_pack(float x0, float x1, uint32_t& hp, uint32_t& lp) {
    __nv_bfloat16 h0 = __float2bfloat16(x0);
    __nv_bfloat16 h1 = __float2bfloat16(x1);
    __nv_bfloat16 l0 = __float2bfloat16(x0 - __bfloat162float(h0));
    __nv_bfloat16 l1 = __float2bfloat16(x1 - __bfloat162float(h1));
    hp = ((uint32_t)__bfloat16_as_ushort(h1) << 16) | __bfloat16_as_ushort(h0);
    lp = ((uint32_t)__bfloat16_as_ushort(l1) << 16) | __bfloat16_as_ushort(l0);
}

// ---------------- fused prep kernel: count || convA || convB1 || convB2 -----
#define NB_COUNT 313
#define NB_CONVA 2500
#define NB_CONVB1 768
#define NB_CONVB2 192
#define NB_PREP (NB_COUNT + NB_CONVA + NB_CONVB1 + NB_CONVB2)

__device__ __forceinline__ void convB_body(const float* __restrict__ W,
                                           __nv_bfloat16* __restrict__ Bx,
                                           int t, int NOUT) {
    int r = t / NOUT, n = t - r * NOUT;
    int seg = r >> 8, k = r & 255;
    float w = W[(size_t)k * NOUT + n];
    __nv_bfloat16 hi = __float2bfloat16(w);
    Bx[t] = (seg == 1) ? __float2bfloat16(w - __bfloat162float(hi)) : hi;
}

__global__ __launch_bounds__(256) void prep_kernel(
    const int4* __restrict__ dst4, const float* __restrict__ in_feat,
    const float* __restrict__ W1, const float* __restrict__ W2) {
    const int tid = threadIdx.x;
    int b = blockIdx.x;
    if (b < NB_COUNT) {
        int t = b * 256 + tid;
        if (t < NE / 4) {
            int4 d = dst4[t];
            atomicAdd(&g_counts[d.x], 1);
            atomicAdd(&g_counts[d.y], 1);
            atomicAdd(&g_counts[d.z], 1);
            atomicAdd(&g_counts[d.w], 1);
        }
    } else if (b < NB_COUNT + NB_CONVA) {
        int t = (b - NB_COUNT) * 256 + tid;
        int row = t >> 5, c8 = t & 31;
        const float4* p = (const float4*)(in_feat + (size_t)row * 256 + c8 * 8);
        float4 v0 = p[0], v1 = p[1];
        uint32_t hp[4], lp[4];
        split_pack(v0.x, v0.y, hp[0], lp[0]);
        split_pack(v0.z, v0.w, hp[1], lp[1]);
        split_pack(v1.x, v1.y, hp[2], lp[2]);
        split_pack(v1.z, v1.w, hp[3], lp[3]);
        *(uint4*)(g_A2 + (size_t)row * 512 + c8 * 8)       = make_uint4(hp[0], hp[1], hp[2], hp[3]);
        *(uint4*)(g_A2 + (size_t)row * 512 + 256 + c8 * 8) = make_uint4(lp[0], lp[1], lp[2], lp[3]);
    } else if (b < NB_COUNT + NB_CONVA + NB_CONVB1) {
        int t = (b - NB_COUNT - NB_CONVA) * 256 + tid;
        convB_body(W1, g_Bx1, t, 256);
    } else {
        int t = (b - NB_COUNT - NB_CONVA - NB_CONVB1) * 256 + tid;
        convB_body(W2, g_Bx2, t, 64);
    }
}

// ---------------- scan (row offsets) ----------------------------------------
__global__ void scan_kernel() {
    __shared__ int ssum[1024];
    const int tid = threadIdx.x;
    const int CH  = (NN + 1023) / 1024;
    const int base = tid * CH;
    int s = 0;
    for (int i = 0; i < CH; i++) {
        int idx = base + i;
        if (idx < NN) s += g_counts[idx];
    }
    ssum[tid] = s;
    __syncthreads();
    for (int off = 1; off < 1024; off <<= 1) {
        int v = 0;
        if (tid >= off) v = ssum[tid - off];
        __syncthreads();
        ssum[tid] += v;
        __syncthreads();
    }
    int run = (tid == 0) ? 0 : ssum[tid - 1];
    for (int i = 0; i < CH; i++) {
        int idx = base + i;
        if (idx < NN) {
            g_row_off[idx] = run;
            g_cursor[idx]  = run;
            run += g_counts[idx];
        }
    }
    if (tid == 0) g_row_off[NN] = ssum[1023];
}

// ---------------- GEMM block device function --------------------------------
// A2: [NN,512] hi|lo.  Bx: [768,NOUT].  k_ext segs: (Ahi,Bhi),(Ahi,Blo),(Alo,Bhi)
template <int BM, int BN, int STAGES>
struct __align__(16) GemmSmem {
    __nv_bfloat16 As[STAGES][BM * 40];  // 80B padded rows (BK=32)
    __nv_bfloat16 Bs[STAGES][32 * BN];
    float s_el[(BN / 64) * BM], s_er[(BN / 64) * BM];
    float s_al[BN], s_ar[BN];
};

template <int BM, int BN, int WARPS_M, int WARPS_N, int TOTHEADS, int STAGES>
__device__ void gemm_block(
    int bxx, int byy, GemmSmem<BM, BN, STAGES>& S,
    const __nv_bfloat16* __restrict__ Bx, __half* __restrict__ Fh,
    const float* __restrict__ al, const float* __restrict__ ar,
    float* __restrict__ elo, float* __restrict__ ero, int NOUT) {
    constexpr int WM = BM / WARPS_M;
    constexpr int WN = BN / WARPS_N;
    constexpr int MI = WM / 16;
    constexpr int NI = WN / 8;
    constexpr int BCH = BN / 8;
    constexpr int NK = KEXT / 32;        // 24
    constexpr int HPB = BN / 64;

    const int tid = threadIdx.x;
    const int warp = tid >> 5, lane = tid & 31;
    const int wm = warp / WARPS_N, wn = warp % WARPS_N;
    const int m0 = byy * BM;
    const int n0 = bxx * BN;

    for (int i = tid; i < HPB * BM; i += 256) { S.s_el[i] = 0.f; S.s_er[i] = 0.f; }
    for (int i = tid; i < BN; i += 256) { S.s_al[i] = al[n0 + i]; S.s_ar[i] = ar[n0 + i]; }

    uint32_t asb[STAGES], bsb[STAGES];
#pragma unroll
    for (int s = 0; s < STAGES; s++) {
        asb[s] = smem_u32(&S.As[s][0]);
        bsb[s] = smem_u32(&S.Bs[s][0]);
    }

    float acc[MI][NI][4];
#pragma unroll
    for (int mi = 0; mi < MI; mi++)
#pragma unroll
        for (int ni = 0; ni < NI; ni++)
#pragma unroll
            for (int q = 0; q < 4; q++) acc[mi][ni][q] = 0.f;

    auto load_stage = [&](int kt, int buf) {
        int k0e = kt * 32;
        int seg = k0e >> 8;
        int acol = ((seg == 2) ? 256 : 0) + (k0e & 255);
#pragma unroll
        for (int i = tid; i < BM * 4; i += 256) {
            int r = i >> 2, c = i & 3;
            cp16(asb[buf] + r * 80 + c * 16,
                 g_A2 + (size_t)(m0 + r) * 512 + acol + c * 8,
                 (m0 + r) < NN);
        }
#pragma unroll
        for (int i = tid; i < 32 * BCH; i += 256) {
            int r = i / BCH, c = i - r * BCH;
            int cp = c ^ (r & 7);
            cp16(bsb[buf] + r * (BN * 2) + cp * 16,
                 Bx + (size_t)(k0e + r) * NOUT + n0 + c * 8, true);
        }
        CP_COMMIT();
    };

#pragma unroll
    for (int s = 0; s < STAGES - 1; s++) load_stage(s, s);

    for (int kt = 0; kt < NK; kt++) {
        if constexpr (STAGES == 2)
            asm volatile("cp.async.wait_group 0;" ::: "memory");
        else if constexpr (STAGES == 3)
            asm volatile("cp.async.wait_group 1;" ::: "memory");
        else
            asm volatile("cp.async.wait_group 2;" ::: "memory");
        __syncthreads();
        if (kt + STAGES - 1 < NK) load_stage(kt + STAGES - 1, (kt + STAGES - 1) % STAGES);
        const int buf = kt % STAGES;

#pragma unroll
        for (int ks = 0; ks < 32; ks += 16) {
            uint32_t af[MI][4];
#pragma unroll
            for (int mi = 0; mi < MI; mi++) {
                int row = wm * WM + mi * 16 + (lane & 15);
                int ch = (ks >> 3) + (lane >> 4);
                LDSM_X4(af[mi][0], af[mi][1], af[mi][2], af[mi][3],
                        asb[buf] + row * 80 + ch * 16);
            }
            uint32_t bfr[NI][2];
#pragma unroll
            for (int ni2 = 0; ni2 < NI / 2; ni2++) {
                int krow = ks + (lane & 7) + ((lane >> 3) & 1) * 8;
                int c = (wn * WN) / 8 + ni2 * 2 + (lane >> 4);
                int cp = c ^ (krow & 7);
                uint32_t r0, r1, r2, r3;
                LDSM_X4_T(r0, r1, r2, r3, bsb[buf] + krow * (BN * 2) + cp * 16);
                bfr[ni2 * 2][0] = r0; bfr[ni2 * 2][1] = r1;
                bfr[ni2 * 2 + 1][0] = r2; bfr[ni2 * 2 + 1][1] = r3;
            }
#pragma unroll
            for (int mi = 0; mi < MI; mi++)
#pragma unroll
                for (int ni = 0; ni < NI; ni++)
                    MMA_BF16(acc[mi][ni], af[mi], bfr[ni]);
        }
    }

    // epilogue: fp16 feat store + fused el/er
#pragma unroll
    for (int mi = 0; mi < MI; mi++) {
        int lrow = wm * WM + mi * 16 + (lane >> 2);
        int grow = m0 + lrow;
        float el0 = 0.f, er0 = 0.f, el8 = 0.f, er8 = 0.f;
#pragma unroll
        for (int ni = 0; ni < NI; ni++) {
            int lcol = wn * WN + ni * 8 + (lane & 3) * 2;
            int gcol = n0 + lcol;
            float av0 = S.s_al[lcol], av1 = S.s_al[lcol + 1];
            float rv0 = S.s_ar[lcol], rv1 = S.s_ar[lcol + 1];
            el0 += acc[mi][ni][0] * av0 + acc[mi][ni][1] * av1;
            er0 += acc[mi][ni][0] * rv0 + acc[mi][ni][1] * rv1;
            el8 += acc[mi][ni][2] * av0 + acc[mi][ni][3] * av1;
            er8 += acc[mi][ni][2] * rv0 + acc[mi][ni][3] * rv1;
            if (grow < NN)
                *(__half2*)(Fh + (size_t)grow * NOUT + gcol) =
                    __floats2half2_rn(acc[mi][ni][0], acc[mi][ni][1]);
            if (grow + 8 < NN)
                *(__half2*)(Fh + (size_t)(grow + 8) * NOUT + gcol) =
                    __floats2half2_rn(acc[mi][ni][2], acc[mi][ni][3]);
        }
#pragma unroll
        for (int off = 1; off <= 2; off <<= 1) {
            el0 += __shfl_xor_sync(0xffffffffu, el0, off);
            er0 += __shfl_xor_sync(0xffffffffu, er0, off);
            el8 += __shfl_xor_sync(0xffffffffu, el8, off);
            er8 += __shfl_xor_sync(0xffffffffu, er8, off);
        }
        if ((lane & 3) == 0) {
            int hl = (wn * WN) >> 6;
            if (grow < NN) {
                atomicAdd(&S.s_el[hl * BM + lrow], el0);
                atomicAdd(&S.s_er[hl * BM + lrow], er0);
            }
            if (grow + 8 < NN) {
                atomicAdd(&S.s_el[hl * BM + lrow + 8], el8);
                atomicAdd(&S.s_er[hl * BM + lrow + 8], er8);
            }
        }
    }
    __syncthreads();
    for (int i = tid; i < HPB * BM; i += 256) {
        int hl = i / BM, r = i % BM;
        int grow = m0 + r;
        if (grow < NN) {
            int gh = (n0 >> 6) + hl;
            elo[grow * TOTHEADS + gh] = S.s_el[i];
            ero[grow * TOTHEADS + gh] = S.s_er[i];
        }
    }
}

// ---------------- fused scatter || GEMM1 ------------------------------------
#define NB_GEMM1 314   // 2 x 157

__global__ __launch_bounds__(256) void scatter_gemm1_kernel(
    const int4* __restrict__ src4, const int4* __restrict__ dst4,
    const __nv_bfloat16* __restrict__ Bx, __half* __restrict__ Fh,
    const float* __restrict__ al, const float* __restrict__ ar,
    float* __restrict__ elo, float* __restrict__ ero) {
    __shared__ GemmSmem<128, 128, 2> S;
    int b = blockIdx.x;
    if (b < NB_GEMM1) {
        gemm_block<128, 128, 2, 4, 4, 2>(b & 1, b >> 1, S, Bx, Fh, al, ar, elo, ero, 256);
    } else {
        int t = (b - NB_GEMM1) * 256 + threadIdx.x;
        if (t < NE / 4) {
            int4 s = src4[t];
            int4 d = dst4[t];
            g_csr_src[atomicAdd(&g_cursor[d.x], 1)] = s.x;
            g_csr_src[atomicAdd(&g_cursor[d.y], 1)] = s.y;
            g_csr_src[atomicAdd(&g_cursor[d.z], 1)] = s.z;
            g_csr_src[atomicAdd(&g_cursor[d.w], 1)] = s.w;
        }
    }
}

// gemm2: BM=64 tiles (313 CTAs), 4-stage pipeline, 4x2 warp grid (static smem)
__global__ __launch_bounds__(256) void gemm2_kernel(
    const __nv_bfloat16* __restrict__ Bx, __half* __restrict__ Fh,
    const float* __restrict__ al, const float* __restrict__ ar,
    float* __restrict__ elo, float* __restrict__ ero) {
    __shared__ GemmSmem<64, 64, 4> S;
    gemm_block<64, 64, 4, 2, 1, 4>(0, blockIdx.x, S, Bx, Fh, al, ar, elo, ero, 64);
}

// ---------------- layer-1 softmax-aggregate + bias + ELU -> split-bf16 A2 ---
// 1 warp per node; 8 lanes/head, 8 feats/lane (uint4 gathers).
// Exp dedup: per 8-edge chunk, lane h*8+g computes exp for edge g only;
// (x, s) pairs distributed to the head's 8 lanes via shuffles.
// max-shift dropped: logits bounded, exp cannot overflow, softmax shift-invariant
__global__ void agg1_kernel(const float* __restrict__ b1) {
    int gw   = (blockIdx.x * blockDim.x + threadIdx.x) >> 5;
    int lane = threadIdx.x & 31;
    if (gw >= NN) return;
    const int beg = g_row_off[gw];
    const int end = g_row_off[gw + 1];
    const int head = lane >> 3;
    const int g    = lane & 7;
    const int hbase = lane & 24;
    const int f0   = lane * 8;
    const float er = g_er1[gw * 4 + head];

    float acc[8];
#pragma unroll
    for (int j = 0; j < 8; j++) acc[j] = 0.f;
    float den = 0.f;

    int i = beg;
    for (; i + 8 <= end; i += 8) {
        int s_own = g_csr_src[i + g];
        float e = g_el1[s_own * 4 + head] + er;
        e = (e > 0.f) ? e : 0.2f * e;
        float x_own = __expf(e);
#pragma unroll
        for (int half8 = 0; half8 < 8; half8 += 4) {
            float xj[4];
            int   sj[4];
#pragma unroll
            for (int j = 0; j < 4; j++) {
                xj[j] = __shfl_sync(0xffffffffu, x_own, hbase | (half8 + j));
                sj[j] = __shfl_sync(0xffffffffu, s_own, hbase | (half8 + j));
            }
            uint4 u0 = *(const uint4*)(g_feat1h + (size_t)sj[0] * 256 + f0);
            uint4 u1 = *(const uint4*)(g_feat1h + (size_t)sj[1] * 256 + f0);
            uint4 u2 = *(const uint4*)(g_feat1h + (size_t)sj[2] * 256 + f0);
            uint4 u3 = *(const uint4*)(g_feat1h + (size_t)sj[3] * 256 + f0);
            den += (xj[0] + xj[1]) + (xj[2] + xj[3]);
            const __half2* h0 = (const __half2*)&u0;
            const __half2* h1 = (const __half2*)&u1;
            const __half2* h2 = (const __half2*)&u2;
            const __half2* h3 = (const __half2*)&u3;
#pragma unroll
            for (int q = 0; q < 4; q++) {
                float2 v0 = __half22float2(h0[q]);
                float2 v1 = __half22float2(h1[q]);
                float2 v2 = __half22float2(h2[q]);
                float2 v3 = __half22float2(h3[q]);
                acc[2 * q]     = fmaf(xj[0], v0.x, fmaf(xj[1], v1.x, fmaf(xj[2], v2.x, fmaf(xj[3], v3.x, acc[2 * q]))));
                acc[2 * q + 1] = fmaf(xj[0], v0.y, fmaf(xj[1], v1.y, fmaf(xj[2], v2.y, fmaf(xj[3], v3.y, acc[2 * q + 1]))));
            }
        }
    }
    for (; i < end; i++) {
        int s = g_csr_src[i];
        float e = g_el1[s * 4 + head] + er;
        e = (e > 0.f) ? e : 0.2f * e;
        float ex = __expf(e);
        den += ex;
        uint4 u = *(const uint4*)(g_feat1h + (size_t)s * 256 + f0);
        const __half2* hh = (const __half2*)&u;
#pragma unroll
        for (int q = 0; q < 4; q++) {
            float2 v = __half22float2(hh[q]);
            acc[2 * q]     = fmaf(ex, v.x, acc[2 * q]);
            acc[2 * q + 1] = fmaf(ex, v.y, acc[2 * q + 1]);
        }
    }

    float inv = (den > 0.f) ? (1.0f / den) : 0.f;
    float o[8];
#pragma unroll
    for (int j = 0; j < 8; j++) {
        float v = acc[j] * inv + b1[f0 + j];
        o[j] = (v > 0.f) ? v : (__expf(v) - 1.0f);   // ELU
    }
    // write split-bf16 A2 row directly (layer2 GEMM operand)
    uint32_t hp[4], lp[4];
    split_pack(o[0], o[1], hp[0], lp[0]);
    split_pack(o[2], o[3], hp[1], lp[1]);
    split_pack(o[4], o[5], hp[2], lp[2]);
    split_pack(o[6], o[7], hp[3], lp[3]);
    *(uint4*)(g_A2 + (size_t)gw * 512 + f0)       = make_uint4(hp[0], hp[1], hp[2], hp[3]);
    *(uint4*)(g_A2 + (size_t)gw * 512 + 256 + f0) = make_uint4(lp[0], lp[1], lp[2], lp[3]);
}

// ---------------- layer-2 softmax-aggregate + bias --------------------------
// Exp dedup via width-4 shuffles: lane (lane&3)=q computes exp for edge q.
__global__ void agg2_kernel(const float* __restrict__ b2, float* __restrict__ out) {
    int gw   = (blockIdx.x * blockDim.x + threadIdx.x) >> 5;
    int lane = threadIdx.x & 31;
    if (gw >= NN) return;
    const int beg = g_row_off[gw];
    const int end = g_row_off[gw + 1];
    const float er = g_er2[gw];
    const int q = lane & 3;

    float a0 = 0.f, a1 = 0.f, den = 0.f;
    int i = beg;
    for (; i + 4 <= end; i += 4) {
        int s_own = g_csr_src[i + q];
        float e = g_el2[s_own] + er;
        e = (e > 0.f) ? e : 0.2f * e;
        float x_own = __expf(e);
        float xj[4];
        int   sj[4];
#pragma unroll
        for (int j = 0; j < 4; j++) {
            xj[j] = __shfl_sync(0xffffffffu, x_own, j, 4);
            sj[j] = __shfl_sync(0xffffffffu, s_own, j, 4);
        }
        den += (xj[0] + xj[1]) + (xj[2] + xj[3]);
        float2 v0 = __half22float2(*(const __half2*)(g_feat2h + (size_t)sj[0] * 64 + lane * 2));
        float2 v1 = __half22float2(*(const __half2*)(g_feat2h + (size_t)sj[1] * 64 + lane * 2));
        float2 v2 = __half22float2(*(const __half2*)(g_feat2h + (size_t)sj[2] * 64 + lane * 2));
        float2 v3 = __half22float2(*(const __half2*)(g_feat2h + (size_t)sj[3] * 64 + lane * 2));
        a0 = fmaf(xj[0], v0.x, fmaf(xj[1], v1.x, fmaf(xj[2], v2.x, fmaf(xj[3], v3.x, a0))));
        a1 = fmaf(xj[0], v0.y, fmaf(xj[1], v1.y, fmaf(xj[2], v2.y, fmaf(xj[3], v3.y, a1))));
    }
    for (; i < end; i++) {
        int s = g_csr_src[i];
        float e = g_el2[s] + er;
        e = (e > 0.f) ? e : 0.2f * e;
        float ex = __expf(e);
        den += ex;
        float2 v = __half22float2(*(const __half2*)(g_feat2h + (size_t)s * 64 + lane * 2));
        a0 = fmaf(ex, v.x, a0);
        a1 = fmaf(ex, v.y, a1);
    }
    float inv = (den > 0.f) ? (1.0f / den) : 0.f;
    float2 r = make_float2(a0 * inv + b2[lane * 2], a1 * inv + b2[lane * 2 + 1]);
    *(float2*)(out + (size_t)gw * 64 + lane * 2) = r;
}

// ---------------- launcher ---------------------------------------------------
extern "C" void kernel_launch(void* const* d_in, const int* in_sizes, int n_in,
                              void* d_out, int out_size) {
    const float* in_feat = (const float*)d_in[0];
    const float* W1      = (const float*)d_in[1];
    const float* al1     = (const float*)d_in[2];
    const float* ar1     = (const float*)d_in[3];
    const float* b1      = (const float*)d_in[4];
    const float* W2      = (const float*)d_in[5];
    const float* al2     = (const float*)d_in[6];
    const float* ar2     = (const float*)d_in[7];
    const float* b2      = (const float*)d_in[8];
    const int*   src     = (const int*)d_in[9];
    const int*   dst     = (const int*)d_in[10];
    float*       out     = (float*)d_out;

    __half *f1h, *f2h;
    float *el1, *er1, *el2, *er2;
    __nv_bfloat16 *bx1, *bx2;
    int* counts;
    cudaGetSymbolAddress((void**)&f1h, g_feat1h);
    cudaGetSymbolAddress((void**)&f2h, g_feat2h);
    cudaGetSymbolAddress((void**)&el1, g_el1);
    cudaGetSymbolAddress((void**)&er1, g_er1);
    cudaGetSymbolAddress((void**)&el2, g_el2);
    cudaGetSymbolAddress((void**)&er2, g_er2);
    cudaGetSymbolAddress((void**)&bx1, g_Bx1);
    cudaGetSymbolAddress((void**)&bx2, g_Bx2);
    cudaGetSymbolAddress((void**)&counts, g_counts);

    // zero counts (memset node)
    cudaMemsetAsync(counts, 0, NN * sizeof(int));

    // K1: count || convA || convB1 || convB2
    prep_kernel<<<NB_PREP, 256>>>((const int4*)dst, in_feat, W1, W2);

    // K2: row-offset scan (1024 threads)
    scan_kernel<<<1, 1024>>>();

    // K3: scatter || GEMM1 (+fused el/er, fp16 feat store)
    scatter_gemm1_kernel<<<NB_GEMM1 + NB_COUNT, 256>>>(
        (const int4*)src, (const int4*)dst, bx1, f1h, al1, ar1, el1, er1);

    // K4: layer-1 aggregate -> split-bf16 A2  (exp-dedup via shuffles)
    agg1_kernel<<<(NN * 32 + 255) / 256, 256>>>(b1);

    // K5: layer-2 GEMM (BM=64, 4-stage pipeline, 313 CTAs)
    gemm2_kernel<<<(NN + 63) / 64, 256>>>(bx2, f2h, al2, ar2, el2, er2);

    // K6: layer-2 aggregate (exp-dedup via width-4 shuffles)
    agg2_kernel<<<(NN * 32 + 255) / 256, 256>>>(b2, out);
}